// round 16
// baseline (speedup 1.0000x reference)
#include <cuda_runtime.h>
#include <math_constants.h>

// Problem shapes (fixed by the reference)
constexpr int NB = 64;     // batch
constexpr int NT = 2048;   // time
constexpr int NH = 512;    // listener hidden
constexpr int NS = 512;    // decoder state
constexpr int NK = 128;    // key dim
constexpr int NV = 128;    // value dim
constexpr int NCH = 16;    // t-chunks per batch
constexpr int RPC = 128;   // rows per chunk
constexpr int TILE = 8;    // rows per smem tile (16 KB)
constexpr int NTILES = RPC / TILE;  // 16
constexpr float F_EPS = 1e-12f;

// Scratch (allocation-free rule: __device__ globals)
__device__ float g_q[NB * NK];
__device__ float g_qh[NB * NH];
__device__ float g_c[NB];
__device__ float g_energy[NB * NT];
__device__ float g_pm[NB * NCH];
__device__ float g_pZ[NB * NCH];
__device__ float g_pSm[NB * NCH];
__device__ float g_pacc[NB * NCH * NH];   // 2 MB

__device__ __forceinline__ unsigned smem_u32(const void* p) {
    return (unsigned)__cvta_generic_to_shared(p);
}

// ---------------------------------------------------------------------------
// Kernel 1a: q[b, kg*16 .. +16] = dec[b] . Ws rows + bs   (grid (NB,8))
// ---------------------------------------------------------------------------
__global__ void __launch_bounds__(128)
kq1(const float* __restrict__ dec_state,
    const float* __restrict__ Ws, const float* __restrict__ bs) {
    __shared__ float dec[NS];
    int b = blockIdx.x, kg = blockIdx.y;
    int tid = threadIdx.x, warp = tid >> 5, lane = tid & 31;

    for (int i = tid; i < NS; i += 128) dec[i] = dec_state[b * NS + i];
    __syncthreads();

    const float4* dec4 = (const float4*)dec;
    int k0 = kg * 16 + warp * 4;
    const float4* w0 = (const float4*)(Ws + (size_t)(k0 + 0) * NS);
    const float4* w1 = (const float4*)(Ws + (size_t)(k0 + 1) * NS);
    const float4* w2 = (const float4*)(Ws + (size_t)(k0 + 2) * NS);
    const float4* w3 = (const float4*)(Ws + (size_t)(k0 + 3) * NS);
    float a0 = 0.f, a1 = 0.f, a2 = 0.f, a3 = 0.f;
    #pragma unroll
    for (int j = 0; j < 4; ++j) {
        int idx = lane + 32 * j;
        float4 dd = dec4[idx];
        float4 x0 = w0[idx], x1 = w1[idx], x2 = w2[idx], x3 = w3[idx];
        a0 += dd.x * x0.x + dd.y * x0.y + dd.z * x0.z + dd.w * x0.w;
        a1 += dd.x * x1.x + dd.y * x1.y + dd.z * x1.z + dd.w * x1.w;
        a2 += dd.x * x2.x + dd.y * x2.y + dd.z * x2.z + dd.w * x2.w;
        a3 += dd.x * x3.x + dd.y * x3.y + dd.z * x3.z + dd.w * x3.w;
    }
    #pragma unroll
    for (int o = 16; o; o >>= 1) {
        a0 += __shfl_xor_sync(0xffffffffu, a0, o);
        a1 += __shfl_xor_sync(0xffffffffu, a1, o);
        a2 += __shfl_xor_sync(0xffffffffu, a2, o);
        a3 += __shfl_xor_sync(0xffffffffu, a3, o);
    }
    if (lane == 0) {
        g_q[b * NK + k0 + 0] = a0 + bs[k0 + 0];
        g_q[b * NK + k0 + 1] = a1 + bs[k0 + 1];
        g_q[b * NK + k0 + 2] = a2 + bs[k0 + 2];
        g_q[b * NK + k0 + 3] = a3 + bs[k0 + 3];
    }
}

// ---------------------------------------------------------------------------
// Kernel 1b: qh[b, hg*128 .. +128] = sum_k q[b,k] * Wh[k,h]   (grid (NB,4))
// Fires launch_dependents at entry so the PDL-attributed k_fused can begin
// its (qh-independent) tile-0 prefetch while kq2 runs.
// ---------------------------------------------------------------------------
__global__ void __launch_bounds__(128)
kq2(const float* __restrict__ Wh, const float* __restrict__ bh) {
    asm volatile("griddepcontrol.launch_dependents;" ::: "memory");

    __shared__ float q[NK];
    __shared__ float4 part[4][32];
    int b = blockIdx.x, hg = blockIdx.y;
    int tid = threadIdx.x, warp = tid >> 5, lane = tid & 31;

    q[tid] = g_q[b * NK + tid];
    __syncthreads();

    int h4l = tid & 31;
    int kg  = tid >> 5;
    const float4* wh4 = (const float4*)Wh;   // [k][128]
    float4 a = make_float4(0.f, 0.f, 0.f, 0.f);
    #pragma unroll
    for (int kk = 0; kk < 32; ++kk) {
        int k = kg * 32 + kk;
        float qk = q[k];
        float4 w = wh4[(size_t)k * 128 + hg * 32 + h4l];
        a.x += qk * w.x; a.y += qk * w.y; a.z += qk * w.z; a.w += qk * w.w;
    }
    part[kg][h4l] = a;
    __syncthreads();

    if (tid < 32) {
        float4 p0 = part[0][tid], p1 = part[1][tid], p2 = part[2][tid], p3 = part[3][tid];
        float4 s = make_float4(p0.x + p1.x + p2.x + p3.x,
                               p0.y + p1.y + p2.y + p3.y,
                               p0.z + p1.z + p2.z + p3.z,
                               p0.w + p1.w + p2.w + p3.w);
        ((float4*)(g_qh + b * NH))[hg * 32 + tid] = s;
    }
    if (hg == 0 && warp == 1) {
        float cc = 0.f;
        #pragma unroll
        for (int k = lane; k < NK; k += 32) cc += q[k] * bh[k];
        #pragma unroll
        for (int o = 16; o; o >>= 1) cc += __shfl_xor_sync(0xffffffffu, cc, o);
        if (lane == 0) g_c[b] = cc;
    }
}

// ---------------------------------------------------------------------------
// Kernel 2 (FUSED, warp-private online softmax): cp.async double-buffered
// 8-row tiles; PDL: tile-0 prefetch issued BEFORE griddepcontrol.wait, so
// the DRAM ramp overlaps kq2's tail. Rest identical to the 66.6 µs build.
// ---------------------------------------------------------------------------
__global__ void __launch_bounds__(256)
k_fused(const float* __restrict__ listener, const int* __restrict__ len) {
    __shared__ float s_buf[2][TILE * NH];   // 32 KB
    __shared__ float s_m[8], s_Z[8], s_Sm[8];

    int b = blockIdx.x, ch = blockIdx.y;
    int tid = threadIdx.x, warp = tid >> 5, lane = tid & 31;
    int tbase = ch * RPC;

    const float* gbase = listener + ((size_t)b * NT + tbase) * NH;

    // prologue: tile 0 prefetch (independent of kq outputs)
    {
        unsigned sdst = smem_u32(&s_buf[0][0]);
        #pragma unroll
        for (int i = 0; i < 4; ++i) {
            int e4 = tid + 256 * i;
            asm volatile("cp.async.cg.shared.global [%0], [%1], 16;\n"
                         :: "r"(sdst + e4 * 16), "l"(gbase + e4 * 4));
        }
        asm volatile("cp.async.commit_group;\n" ::: "memory");
    }

    // wait for kq2's writes (g_qh, g_c) to be visible
    asm volatile("griddepcontrol.wait;" ::: "memory");

    int L = (b == 0) ? NT : len[b];
    float c = g_c[b];
    const float4* qh4 = (const float4*)(g_qh + b * NH);
    float4 q[4];
    #pragma unroll
    for (int j = 0; j < 4; ++j) q[j] = qh4[lane + 32 * j];

    float4 acc[4];
    #pragma unroll
    for (int j = 0; j < 4; ++j) acc[j] = make_float4(0.f, 0.f, 0.f, 0.f);
    float m = -CUDART_INF_F, Z = 0.f, Sm = 0.f;

    for (int tile = 0; tile < NTILES; ++tile) {
        int cur = tile & 1;
        asm volatile("cp.async.wait_group 0;\n" ::: "memory");
        __syncthreads();

        if (tile + 1 < NTILES) {
            unsigned sdst = smem_u32(&s_buf[1 - cur][0]);
            const float* gsrc = gbase + (size_t)(tile + 1) * TILE * NH;
            #pragma unroll
            for (int i = 0; i < 4; ++i) {
                int e4 = tid + 256 * i;
                asm volatile("cp.async.cg.shared.global [%0], [%1], 16;\n"
                             :: "r"(sdst + e4 * 16), "l"(gsrc + e4 * 4));
            }
            asm volatile("cp.async.commit_group;\n" ::: "memory");
        }

        const float* buf = s_buf[cur];
        const float4* row4 = (const float4*)(buf + warp * NH);
        float4 v[4];
        #pragma unroll
        for (int j = 0; j < 4; ++j) v[j] = row4[lane + 32 * j];

        float d = 0.f;
        #pragma unroll
        for (int j = 0; j < 4; ++j)
            d += v[j].x * q[j].x + v[j].y * q[j].y + v[j].z * q[j].z + v[j].w * q[j].w;
        #pragma unroll
        for (int o = 16; o; o >>= 1) d += __shfl_xor_sync(0xffffffffu, d, o);
        float e = d + c;
        int trow = tbase + tile * TILE + warp;
        if (lane == 0) g_energy[b * NT + trow] = e;

        float mnew = fmaxf(m, e);
        float sc = __expf(m - mnew);     // first tile: exp(-inf) = 0
        float x  = __expf(e - mnew);
        bool valid = trow < L;
        Z  = Z  * sc + x;
        Sm = Sm * sc + (valid ? x : 0.f);
        float w = valid ? x : 0.f;
        m = mnew;
        #pragma unroll
        for (int j = 0; j < 4; ++j) {
            acc[j].x = acc[j].x * sc + w * v[j].x;
            acc[j].y = acc[j].y * sc + w * v[j].y;
            acc[j].z = acc[j].z * sc + w * v[j].z;
            acc[j].w = acc[j].w * sc + w * v[j].w;
        }
    }

    // --- merge 8 warp partials -> one chunk partial ---
    __syncthreads();
    float4* red = (float4*)&s_buf[0][0];   // [8 warps][128 float4]
    #pragma unroll
    for (int j = 0; j < 4; ++j) red[warp * 128 + lane + 32 * j] = acc[j];
    if (lane == 0) { s_m[warp] = m; s_Z[warp] = Z; s_Sm[warp] = Sm; }
    __syncthreads();

    float mb = s_m[0];
    #pragma unroll
    for (int w = 1; w < 8; ++w) mb = fmaxf(mb, s_m[w]);

    int pc = b * NCH + ch;
    if (tid < 128) {
        float4 s = make_float4(0.f, 0.f, 0.f, 0.f);
        #pragma unroll
        for (int w = 0; w < 8; ++w) {
            float f = __expf(s_m[w] - mb);
            float4 a = red[w * 128 + tid];
            s.x += a.x * f; s.y += a.y * f; s.z += a.z * f; s.w += a.w * f;
        }
        ((float4*)(g_pacc + (size_t)pc * NH))[tid] = s;
    }
    if (tid == 0) {
        float Zb = 0.f, Smb = 0.f;
        #pragma unroll
        for (int w = 0; w < 8; ++w) {
            float f = __expf(s_m[w] - mb);
            Zb += s_Z[w] * f; Smb += s_Sm[w] * f;
        }
        g_pm[pc] = mb; g_pZ[pc] = Zb; g_pSm[pc] = Smb;
    }
}

// ---------------------------------------------------------------------------
// Scalar recompute helper: M, inv, satt from the 48 per-b partial scalars.
// ---------------------------------------------------------------------------
__device__ __forceinline__ void softmax_scalars(int b, float& M, float& inv, float& satt) {
    M = -CUDART_INF_F;
    #pragma unroll
    for (int ci = 0; ci < NCH; ++ci) M = fmaxf(M, g_pm[b * NCH + ci]);
    float Z = 0.f, Sm = 0.f;
    #pragma unroll
    for (int ci = 0; ci < NCH; ++ci) {
        float f = __expf(g_pm[b * NCH + ci] - M);
        Z  += g_pZ[b * NCH + ci]  * f;
        Sm += g_pSm[b * NCH + ci] * f;
    }
    inv = 1.0f / fmaxf(Sm, F_EPS * Z);
    satt = Sm * inv;
}

// ---------------------------------------------------------------------------
// Kernel 3 (epilogue): grid (NB, 8) x 256.
//   vg 0..3: context slice of 32 v rows (redundant ctxh reduce in smem)
//   vg 4..7: attention slice of 512 t (2 per thread)
// ---------------------------------------------------------------------------
__global__ void __launch_bounds__(256)
k_epi(const int* __restrict__ len,
      const float* __restrict__ Wv, const float* __restrict__ bv,
      float* __restrict__ att_out, float* __restrict__ ctx_out) {
    __shared__ float s_f[NCH];
    __shared__ float s_ch[NH];
    int b = blockIdx.x, vg = blockIdx.y;
    int tid = threadIdx.x, warp = tid >> 5, lane = tid & 31;

    float M, inv, satt;
    softmax_scalars(b, M, inv, satt);

    if (vg >= 4) {   // attention path
        int L = (b == 0) ? NT : len[b];
        int t0 = (vg - 4) * 512;
        #pragma unroll
        for (int i = 0; i < 2; ++i) {
            int t = t0 + tid + 256 * i;
            float e = g_energy[b * NT + t];
            att_out[b * NT + t] = (t < L) ? __expf(e - M) * inv : 0.f;
        }
        return;
    }

    // context path
    if (tid < NCH) s_f[tid] = __expf(g_pm[b * NCH + tid] - M);
    __syncthreads();

    #pragma unroll
    for (int i = 0; i < 2; ++i) {
        int h = tid + 256 * i;
        float a = 0.f;
        #pragma unroll
        for (int ci = 0; ci < NCH; ++ci)
            a += g_pacc[(size_t)(b * NCH + ci) * NH + h] * s_f[ci];
        s_ch[h] = a * inv;
    }
    __syncthreads();

    const float4* ch4 = (const float4*)s_ch;
    int v0 = vg * 32 + warp * 4;
    const float4* w0 = (const float4*)(Wv + (size_t)(v0 + 0) * NH);
    const float4* w1 = (const float4*)(Wv + (size_t)(v0 + 1) * NH);
    const float4* w2 = (const float4*)(Wv + (size_t)(v0 + 2) * NH);
    const float4* w3 = (const float4*)(Wv + (size_t)(v0 + 3) * NH);
    float a0 = 0.f, a1 = 0.f, a2 = 0.f, a3 = 0.f;
    #pragma unroll
    for (int j = 0; j < 4; ++j) {
        int idx = lane + 32 * j;
        float4 cc = ch4[idx];
        float4 x0 = w0[idx], x1 = w1[idx], x2 = w2[idx], x3 = w3[idx];
        a0 += cc.x * x0.x + cc.y * x0.y + cc.z * x0.z + cc.w * x0.w;
        a1 += cc.x * x1.x + cc.y * x1.y + cc.z * x1.z + cc.w * x1.w;
        a2 += cc.x * x2.x + cc.y * x2.y + cc.z * x2.z + cc.w * x2.w;
        a3 += cc.x * x3.x + cc.y * x3.y + cc.z * x3.z + cc.w * x3.w;
    }
    #pragma unroll
    for (int o = 16; o; o >>= 1) {
        a0 += __shfl_xor_sync(0xffffffffu, a0, o);
        a1 += __shfl_xor_sync(0xffffffffu, a1, o);
        a2 += __shfl_xor_sync(0xffffffffu, a2, o);
        a3 += __shfl_xor_sync(0xffffffffu, a3, o);
    }
    if (lane == 0) {
        ctx_out[b * NV + v0 + 0] = bv[v0 + 0] * satt + a0;
        ctx_out[b * NV + v0 + 1] = bv[v0 + 1] * satt + a1;
        ctx_out[b * NV + v0 + 2] = bv[v0 + 2] * satt + a2;
        ctx_out[b * NV + v0 + 3] = bv[v0 + 3] * satt + a3;
    }
}

// ---------------------------------------------------------------------------
extern "C" void kernel_launch(void* const* d_in, const int* in_sizes, int n_in,
                              void* d_out, int out_size) {
    const float* dec      = (const float*)d_in[0];
    const float* listener = (const float*)d_in[1];
    const int*   len      = (const int*)d_in[2];
    const float* Ws       = (const float*)d_in[3];
    const float* bs       = (const float*)d_in[4];
    const float* Wh       = (const float*)d_in[5];
    const float* bh       = (const float*)d_in[6];
    const float* Wv       = (const float*)d_in[7];
    const float* bv       = (const float*)d_in[8];

    float* out     = (float*)d_out;
    float* ctx_out = out;                 // (B, V)
    float* att_out = out + NB * NV;       // (B, 1, T)

    kq1<<<dim3(NB, 8), 128>>>(dec, Ws, bs);
    kq2<<<dim3(NB, 4), 128>>>(Wh, bh);

    // k_fused with PDL: may begin (tile-0 prefetch) while kq2 finishes.
    {
        cudaLaunchConfig_t cfg = {};
        cfg.gridDim  = dim3(NB, NCH);
        cfg.blockDim = dim3(256);
        cfg.stream   = 0;
        cudaLaunchAttribute attr[1];
        attr[0].id = cudaLaunchAttributeProgrammaticStreamSerialization;
        attr[0].val.programmaticStreamSerializationAllowed = 1;
        cfg.attrs = attr;
        cfg.numAttrs = 1;
        cudaLaunchKernelEx(&cfg, k_fused, listener, len);
    }

    k_epi<<<dim3(NB, 8), 256>>>(len, Wv, bv, att_out, ctx_out);
}

// round 17
// speedup vs baseline: 1.0965x; 1.0965x over previous
#include <cuda_runtime.h>
#include <math_constants.h>

// Problem shapes (fixed by the reference)
constexpr int NB = 64;     // batch
constexpr int NT = 2048;   // time
constexpr int NH = 512;    // listener hidden
constexpr int NS = 512;    // decoder state
constexpr int NK = 128;    // key dim
constexpr int NV = 128;    // value dim
constexpr int NCH = 8;     // t-chunks per batch (single-wave fused grid)
constexpr int RPC = 256;   // rows per chunk
constexpr int TILE = 8;    // rows per smem tile (16 KB)
constexpr int NTILES = RPC / TILE;  // 32
constexpr float F_EPS = 1e-12f;

// Scratch (allocation-free rule: __device__ globals)
__device__ float g_q[NB * NK];
__device__ float g_qh[NB * NH];
__device__ float g_c[NB];
__device__ float g_energy[NB * NT];
__device__ float g_pm[NB * NCH];
__device__ float g_pZ[NB * NCH];
__device__ float g_pSm[NB * NCH];
__device__ float g_pacc[NB * NCH * NH];   // 1 MB

__device__ __forceinline__ unsigned smem_u32(const void* p) {
    return (unsigned)__cvta_generic_to_shared(p);
}

// ---------------------------------------------------------------------------
// Kernel 1a: q[b, kg*16 .. +16] = dec[b] . Ws rows + bs   (grid (NB,8))
// ---------------------------------------------------------------------------
__global__ void __launch_bounds__(128)
kq1(const float* __restrict__ dec_state,
    const float* __restrict__ Ws, const float* __restrict__ bs) {
    __shared__ float dec[NS];
    int b = blockIdx.x, kg = blockIdx.y;
    int tid = threadIdx.x, warp = tid >> 5, lane = tid & 31;

    for (int i = tid; i < NS; i += 128) dec[i] = dec_state[b * NS + i];
    __syncthreads();

    const float4* dec4 = (const float4*)dec;
    int k0 = kg * 16 + warp * 4;
    const float4* w0 = (const float4*)(Ws + (size_t)(k0 + 0) * NS);
    const float4* w1 = (const float4*)(Ws + (size_t)(k0 + 1) * NS);
    const float4* w2 = (const float4*)(Ws + (size_t)(k0 + 2) * NS);
    const float4* w3 = (const float4*)(Ws + (size_t)(k0 + 3) * NS);
    float a0 = 0.f, a1 = 0.f, a2 = 0.f, a3 = 0.f;
    #pragma unroll
    for (int j = 0; j < 4; ++j) {
        int idx = lane + 32 * j;
        float4 dd = dec4[idx];
        float4 x0 = w0[idx], x1 = w1[idx], x2 = w2[idx], x3 = w3[idx];
        a0 += dd.x * x0.x + dd.y * x0.y + dd.z * x0.z + dd.w * x0.w;
        a1 += dd.x * x1.x + dd.y * x1.y + dd.z * x1.z + dd.w * x1.w;
        a2 += dd.x * x2.x + dd.y * x2.y + dd.z * x2.z + dd.w * x2.w;
        a3 += dd.x * x3.x + dd.y * x3.y + dd.z * x3.z + dd.w * x3.w;
    }
    #pragma unroll
    for (int o = 16; o; o >>= 1) {
        a0 += __shfl_xor_sync(0xffffffffu, a0, o);
        a1 += __shfl_xor_sync(0xffffffffu, a1, o);
        a2 += __shfl_xor_sync(0xffffffffu, a2, o);
        a3 += __shfl_xor_sync(0xffffffffu, a3, o);
    }
    if (lane == 0) {
        g_q[b * NK + k0 + 0] = a0 + bs[k0 + 0];
        g_q[b * NK + k0 + 1] = a1 + bs[k0 + 1];
        g_q[b * NK + k0 + 2] = a2 + bs[k0 + 2];
        g_q[b * NK + k0 + 3] = a3 + bs[k0 + 3];
    }
}

// ---------------------------------------------------------------------------
// Kernel 1b: qh[b, hg*128 .. +128] = sum_k q[b,k] * Wh[k,h]   (grid (NB,4))
// ---------------------------------------------------------------------------
__global__ void __launch_bounds__(128)
kq2(const float* __restrict__ Wh, const float* __restrict__ bh) {
    __shared__ float q[NK];
    __shared__ float4 part[4][32];
    int b = blockIdx.x, hg = blockIdx.y;
    int tid = threadIdx.x, warp = tid >> 5, lane = tid & 31;

    q[tid] = g_q[b * NK + tid];
    __syncthreads();

    int h4l = tid & 31;
    int kg  = tid >> 5;
    const float4* wh4 = (const float4*)Wh;   // [k][128]
    float4 a = make_float4(0.f, 0.f, 0.f, 0.f);
    #pragma unroll
    for (int kk = 0; kk < 32; ++kk) {
        int k = kg * 32 + kk;
        float qk = q[k];
        float4 w = wh4[(size_t)k * 128 + hg * 32 + h4l];
        a.x += qk * w.x; a.y += qk * w.y; a.z += qk * w.z; a.w += qk * w.w;
    }
    part[kg][h4l] = a;
    __syncthreads();

    if (tid < 32) {
        float4 p0 = part[0][tid], p1 = part[1][tid], p2 = part[2][tid], p3 = part[3][tid];
        float4 s = make_float4(p0.x + p1.x + p2.x + p3.x,
                               p0.y + p1.y + p2.y + p3.y,
                               p0.z + p1.z + p2.z + p3.z,
                               p0.w + p1.w + p2.w + p3.w);
        ((float4*)(g_qh + b * NH))[hg * 32 + tid] = s;
    }
    if (hg == 0 && warp == 1) {
        float cc = 0.f;
        #pragma unroll
        for (int k = lane; k < NK; k += 32) cc += q[k] * bh[k];
        #pragma unroll
        for (int o = 16; o; o >>= 1) cc += __shfl_xor_sync(0xffffffffu, cc, o);
        if (lane == 0) g_c[b] = cc;
    }
}

// ---------------------------------------------------------------------------
// Kernel 2 (FUSED, warp-private online softmax): cp.async double-buffered
// 8-row tiles, 1 sync/tile, prefetch after barrier. Grid (NB, 8) = 512
// blocks -> ONE wave at occupancy 4/SM (no wave-2 tail).
// ---------------------------------------------------------------------------
__global__ void __launch_bounds__(256)
k_fused(const float* __restrict__ listener, const int* __restrict__ len) {
    __shared__ float s_buf[2][TILE * NH];   // 32 KB
    __shared__ float s_m[8], s_Z[8], s_Sm[8];

    int b = blockIdx.x, ch = blockIdx.y;
    int tid = threadIdx.x, warp = tid >> 5, lane = tid & 31;
    int L = (b == 0) ? NT : len[b];
    float c = g_c[b];
    int tbase = ch * RPC;

    const float4* qh4 = (const float4*)(g_qh + b * NH);
    float4 q[4];
    #pragma unroll
    for (int j = 0; j < 4; ++j) q[j] = qh4[lane + 32 * j];

    const float* gbase = listener + ((size_t)b * NT + tbase) * NH;

    // prologue: tile 0 (16 KB = 1024 x 16B)
    {
        unsigned sdst = smem_u32(&s_buf[0][0]);
        #pragma unroll
        for (int i = 0; i < 4; ++i) {
            int e4 = tid + 256 * i;
            asm volatile("cp.async.cg.shared.global [%0], [%1], 16;\n"
                         :: "r"(sdst + e4 * 16), "l"(gbase + e4 * 4));
        }
        asm volatile("cp.async.commit_group;\n" ::: "memory");
    }

    float4 acc[4];
    #pragma unroll
    for (int j = 0; j < 4; ++j) acc[j] = make_float4(0.f, 0.f, 0.f, 0.f);
    float m = -CUDART_INF_F, Z = 0.f, Sm = 0.f;

    for (int tile = 0; tile < NTILES; ++tile) {
        int cur = tile & 1;
        asm volatile("cp.async.wait_group 0;\n" ::: "memory");
        __syncthreads();

        if (tile + 1 < NTILES) {
            unsigned sdst = smem_u32(&s_buf[1 - cur][0]);
            const float* gsrc = gbase + (size_t)(tile + 1) * TILE * NH;
            #pragma unroll
            for (int i = 0; i < 4; ++i) {
                int e4 = tid + 256 * i;
                asm volatile("cp.async.cg.shared.global [%0], [%1], 16;\n"
                             :: "r"(sdst + e4 * 16), "l"(gsrc + e4 * 4));
            }
            asm volatile("cp.async.commit_group;\n" ::: "memory");
        }

        const float* buf = s_buf[cur];
        const float4* row4 = (const float4*)(buf + warp * NH);
        float4 v[4];
        #pragma unroll
        for (int j = 0; j < 4; ++j) v[j] = row4[lane + 32 * j];

        float d = 0.f;
        #pragma unroll
        for (int j = 0; j < 4; ++j)
            d += v[j].x * q[j].x + v[j].y * q[j].y + v[j].z * q[j].z + v[j].w * q[j].w;
        #pragma unroll
        for (int o = 16; o; o >>= 1) d += __shfl_xor_sync(0xffffffffu, d, o);
        float e = d + c;
        int trow = tbase + tile * TILE + warp;
        if (lane == 0) g_energy[b * NT + trow] = e;

        float mnew = fmaxf(m, e);
        float sc = __expf(m - mnew);     // first tile: exp(-inf) = 0
        float x  = __expf(e - mnew);
        bool valid = trow < L;
        Z  = Z  * sc + x;
        Sm = Sm * sc + (valid ? x : 0.f);
        float w = valid ? x : 0.f;
        m = mnew;
        #pragma unroll
        for (int j = 0; j < 4; ++j) {
            acc[j].x = acc[j].x * sc + w * v[j].x;
            acc[j].y = acc[j].y * sc + w * v[j].y;
            acc[j].z = acc[j].z * sc + w * v[j].z;
            acc[j].w = acc[j].w * sc + w * v[j].w;
        }
    }

    // --- merge 8 warp partials -> one chunk partial ---
    __syncthreads();
    float4* red = (float4*)&s_buf[0][0];   // [8 warps][128 float4]
    #pragma unroll
    for (int j = 0; j < 4; ++j) red[warp * 128 + lane + 32 * j] = acc[j];
    if (lane == 0) { s_m[warp] = m; s_Z[warp] = Z; s_Sm[warp] = Sm; }
    __syncthreads();

    float mb = s_m[0];
    #pragma unroll
    for (int w = 1; w < 8; ++w) mb = fmaxf(mb, s_m[w]);

    int pc = b * NCH + ch;
    if (tid < 128) {
        float4 s = make_float4(0.f, 0.f, 0.f, 0.f);
        #pragma unroll
        for (int w = 0; w < 8; ++w) {
            float f = __expf(s_m[w] - mb);
            float4 a = red[w * 128 + tid];
            s.x += a.x * f; s.y += a.y * f; s.z += a.z * f; s.w += a.w * f;
        }
        ((float4*)(g_pacc + (size_t)pc * NH))[tid] = s;
    }
    if (tid == 0) {
        float Zb = 0.f, Smb = 0.f;
        #pragma unroll
        for (int w = 0; w < 8; ++w) {
            float f = __expf(s_m[w] - mb);
            Zb += s_Z[w] * f; Smb += s_Sm[w] * f;
        }
        g_pm[pc] = mb; g_pZ[pc] = Zb; g_pSm[pc] = Smb;
    }
}

// ---------------------------------------------------------------------------
// Scalar recompute helper: M, inv, satt from the 24 per-b partial scalars.
// ---------------------------------------------------------------------------
__device__ __forceinline__ void softmax_scalars(int b, float& M, float& inv, float& satt) {
    M = -CUDART_INF_F;
    #pragma unroll
    for (int ci = 0; ci < NCH; ++ci) M = fmaxf(M, g_pm[b * NCH + ci]);
    float Z = 0.f, Sm = 0.f;
    #pragma unroll
    for (int ci = 0; ci < NCH; ++ci) {
        float f = __expf(g_pm[b * NCH + ci] - M);
        Z  += g_pZ[b * NCH + ci]  * f;
        Sm += g_pSm[b * NCH + ci] * f;
    }
    inv = 1.0f / fmaxf(Sm, F_EPS * Z);
    satt = Sm * inv;
}

// ---------------------------------------------------------------------------
// Kernel 3 (epilogue): grid (NB, 8) x 256.
//   vg 0..3: context slice of 32 v rows (redundant ctxh reduce in smem)
//   vg 4..7: attention slice of 512 t (2 per thread)
// ---------------------------------------------------------------------------
__global__ void __launch_bounds__(256)
k_epi(const int* __restrict__ len,
      const float* __restrict__ Wv, const float* __restrict__ bv,
      float* __restrict__ att_out, float* __restrict__ ctx_out) {
    __shared__ float s_f[NCH];
    __shared__ float s_ch[NH];
    int b = blockIdx.x, vg = blockIdx.y;
    int tid = threadIdx.x, warp = tid >> 5, lane = tid & 31;

    float M, inv, satt;
    softmax_scalars(b, M, inv, satt);

    if (vg >= 4) {   // attention path
        int L = (b == 0) ? NT : len[b];
        int t0 = (vg - 4) * 512;
        #pragma unroll
        for (int i = 0; i < 2; ++i) {
            int t = t0 + tid + 256 * i;
            float e = g_energy[b * NT + t];
            att_out[b * NT + t] = (t < L) ? __expf(e - M) * inv : 0.f;
        }
        return;
    }

    // context path
    if (tid < NCH) s_f[tid] = __expf(g_pm[b * NCH + tid] - M);
    __syncthreads();

    #pragma unroll
    for (int i = 0; i < 2; ++i) {
        int h = tid + 256 * i;
        float a = 0.f;
        #pragma unroll
        for (int ci = 0; ci < NCH; ++ci)
            a += g_pacc[(size_t)(b * NCH + ci) * NH + h] * s_f[ci];
        s_ch[h] = a * inv;
    }
    __syncthreads();

    const float4* ch4 = (const float4*)s_ch;
    int v0 = vg * 32 + warp * 4;
    const float4* w0 = (const float4*)(Wv + (size_t)(v0 + 0) * NH);
    const float4* w1 = (const float4*)(Wv + (size_t)(v0 + 1) * NH);
    const float4* w2 = (const float4*)(Wv + (size_t)(v0 + 2) * NH);
    const float4* w3 = (const float4*)(Wv + (size_t)(v0 + 3) * NH);
    float a0 = 0.f, a1 = 0.f, a2 = 0.f, a3 = 0.f;
    #pragma unroll
    for (int j = 0; j < 4; ++j) {
        int idx = lane + 32 * j;
        float4 cc = ch4[idx];
        float4 x0 = w0[idx], x1 = w1[idx], x2 = w2[idx], x3 = w3[idx];
        a0 += cc.x * x0.x + cc.y * x0.y + cc.z * x0.z + cc.w * x0.w;
        a1 += cc.x * x1.x + cc.y * x1.y + cc.z * x1.z + cc.w * x1.w;
        a2 += cc.x * x2.x + cc.y * x2.y + cc.z * x2.z + cc.w * x2.w;
        a3 += cc.x * x3.x + cc.y * x3.y + cc.z * x3.z + cc.w * x3.w;
    }
    #pragma unroll
    for (int o = 16; o; o >>= 1) {
        a0 += __shfl_xor_sync(0xffffffffu, a0, o);
        a1 += __shfl_xor_sync(0xffffffffu, a1, o);
        a2 += __shfl_xor_sync(0xffffffffu, a2, o);
        a3 += __shfl_xor_sync(0xffffffffu, a3, o);
    }
    if (lane == 0) {
        ctx_out[b * NV + v0 + 0] = bv[v0 + 0] * satt + a0;
        ctx_out[b * NV + v0 + 1] = bv[v0 + 1] * satt + a1;
        ctx_out[b * NV + v0 + 2] = bv[v0 + 2] * satt + a2;
        ctx_out[b * NV + v0 + 3] = bv[v0 + 3] * satt + a3;
    }
}

// ---------------------------------------------------------------------------
extern "C" void kernel_launch(void* const* d_in, const int* in_sizes, int n_in,
                              void* d_out, int out_size) {
    const float* dec      = (const float*)d_in[0];
    const float* listener = (const float*)d_in[1];
    const int*   len      = (const int*)d_in[2];
    const float* Ws       = (const float*)d_in[3];
    const float* bs       = (const float*)d_in[4];
    const float* Wh       = (const float*)d_in[5];
    const float* bh       = (const float*)d_in[6];
    const float* Wv       = (const float*)d_in[7];
    const float* bv       = (const float*)d_in[8];

    float* out     = (float*)d_out;
    float* ctx_out = out;                 // (B, V)
    float* att_out = out + NB * NV;       // (B, 1, T)

    kq1    <<<dim3(NB, 8), 128>>>(dec, Ws, bs);
    kq2    <<<dim3(NB, 4), 128>>>(Wh, bh);
    k_fused<<<dim3(NB, NCH), 256>>>(listener, len);
    k_epi  <<<dim3(NB, 8), 256>>>(len, Wv, bv, att_out, ctx_out);
}